// round 13
// baseline (speedup 1.0000x reference)
#include <cuda_runtime.h>
#include <math.h>

// Problem constants
#define B 32
#define S 2048
#define H 1024
#define HV4 (H / 4)          // 256 float4 per row
#define R 64
#define GBLK 32              // d-blocks per batch in K3
#define NUBLK 1024           // u blocks in K2 (1 h-row each)
#define NPREF 512            // prefetch blocks in K1 (4 rubrics each)

// Scratch (no allocations allowed -> __device__ globals)
__device__ float g_ae[B * H];            // answer_emb [B,H]
__device__ float g_u[B * H];             // u = W @ answer_emb, [B,H]
__device__ float g_d[B * S];             // per-unique-row dot d[b,s]
__device__ int   g_list[B * S];          // per-batch compacted touched-row list
__device__ int   g_cnt[B];               // touched-row count per batch
__device__ int   g_arrive[B];            // per-batch arrival counters (K1 zeroes)
__device__ unsigned char g_mask[B * R];  // canonicalized rubric_mask

__device__ __forceinline__ float dot4(float4 a, float4 b) {
    return a.x * b.x + a.y * b.y + a.z * b.z + a.w * b.w;
}

// ---------------------------------------------------------------------------
// K1: ALL input-only work, in one grid (triggers PDL completion at entry).
//   bids [0,256): answer pooling (R10-proven).
//   bids [256,288): per-batch mask canonicalize + span-union mark + compact.
//   bids [288,800): L2 PREFETCH of every rubric-span row (from rspan alone;
//     masked rubrics included -- harmless extra traffic in an idle-DRAM
//     window). prefetch.global.L2 is fire-and-forget: these blocks exit
//     immediately; lines keep streaming into L2 (not flushed per launch),
//     so K3's 86MB read is already in flight ~10us before K3 needs it.
// ---------------------------------------------------------------------------
__global__ void k_prep(const float* __restrict__ seq,
                       const int* __restrict__ aspan,
                       const int* __restrict__ rspan,
                       const unsigned char* __restrict__ rawmask) {
    cudaTriggerProgrammaticLaunchCompletion();
    int tid = threadIdx.x, lane = tid & 31, wid = tid >> 5;

    if (blockIdx.x >= 288) {
        // ---- L2 prefetch: block handles 4 rubrics of one batch ----
        int pid = blockIdx.x - 288;       // 0..511
        int b = pid >> 4, g = pid & 15;   // 16 blocks/batch * 4 rubrics
        const char* sb = (const char*)seq + (size_t)b * S * H * 4;
        #pragma unroll
        for (int rr = 0; rr < 4; rr++) {
            int gi = b * R + g * 4 + rr;
            int r0 = __ldg(rspan + gi * 2), r1 = __ldg(rspan + gi * 2 + 1);
            for (int s = r0 + wid; s < r1; s += 8) {
                const char* p = sb + (size_t)s * (H * 4) + lane * 128;
                asm volatile("prefetch.global.L2 [%0];" :: "l"(p));
            }
        }
        return;
    }

    if (blockIdx.x < 256) {
        // ---- answer pooling ----
        int b = blockIdx.x >> 3, seg = blockIdx.x & 7;
        int s0 = __ldg(aspan + 2 * b), s1 = __ldg(aspan + 2 * b + 1);
        const float4* base =
            (const float4*)(seq + (size_t)b * S * H) + seg * 32 + lane;
        float4 a = make_float4(0.f, 0.f, 0.f, 0.f);
        for (int s = s0 + wid; s < s1; s += 8) {
            float4 e = __ldg(base + s * HV4);
            a.x += e.x; a.y += e.y; a.z += e.z; a.w += e.w;
        }
        __shared__ float4 part[8][32];
        part[wid][lane] = a;
        __syncthreads();
        if (tid < 32) {
            float4 acc = part[0][tid];
            #pragma unroll
            for (int w = 1; w < 8; w++) {
                float4 e = part[w][tid];
                acc.x += e.x; acc.y += e.y; acc.z += e.z; acc.w += e.w;
            }
            float inv = 1.0f / (float)(s1 - s0);
            acc.x *= inv; acc.y *= inv; acc.z *= inv; acc.w *= inv;
            ((float4*)g_ae)[b * HV4 + seg * 32 + tid] = acc;
        }
        return;
    }

    // ---- mark + compact for batch b ----
    int b = blockIdx.x - 256;

    // Encoding detection: int32-coded {0,1} has all bytes at i%4!=0 zero;
    // a 1-byte bool mask (~80% true) has nonzero bytes there w.h.p.
    __shared__ int s_any;
    if (tid == 0) s_any = 0;
    __syncthreads();
    int any = 0;
    for (int i = tid; i < B * R; i += 256)
        if (i & 3) any |= rawmask[i];
    if (any) atomicOr(&s_any, 1);
    __syncthreads();
    const int is_bool = s_any;
    const int* raw32 = (const int*)rawmask;

    __shared__ unsigned char fl[S];
    for (int i = tid; i < S / 4; i += 256) ((int*)fl)[i] = 0;
    __syncthreads();

    // 4 threads per rubric: r = tid>>2, phase jj = tid&3 (same-value byte
    // writes from overlapping rubrics are benign).
    {
        int r = tid >> 2, jj = tid & 3;
        int gi = b * R + r;
        unsigned char m = is_bool ? (rawmask[gi] != 0) : (raw32[gi] != 0);
        if (jj == 0) g_mask[gi] = m;
        if (m) {
            int r0 = __ldg(rspan + gi * 2), r1 = __ldg(rspan + gi * 2 + 1);
            for (int s = r0 + jj; s < r1; s += 4) fl[s] = 1;
        }
    }
    __syncthreads();

    // compact: thread t owns positions [t*8, t*8+8)
    int basep = tid * 8;
    int c = 0;
    #pragma unroll
    for (int k = 0; k < 8; k++) c += fl[basep + k];

    int v = c;
    #pragma unroll
    for (int o = 1; o < 32; o <<= 1) {
        int n = __shfl_up_sync(0xffffffffu, v, o);
        if (lane >= o) v += n;
    }
    __shared__ int wsum[8], wpref[9];
    if (lane == 31) wsum[wid] = v;
    __syncthreads();
    if (tid == 0) {
        int acc = 0;
        for (int w = 0; w < 8; w++) { wpref[w] = acc; acc += wsum[w]; }
        wpref[8] = acc;
    }
    __syncthreads();

    int rank = wpref[wid] + v - c;  // exclusive prefix
    int* list = g_list + b * S;
    #pragma unroll
    for (int k = 0; k < 8; k++)
        if (fl[basep + k]) list[rank++] = basep + k;

    if (tid == 0) {
        g_cnt[b] = wpref[8];
        g_arrive[b] = 0;
    }
}

// ---------------------------------------------------------------------------
// K2 (PDL secondary): u = W @ ae only. One h-row per block.
// Preloads its W row (independent of K1) -> trigger (lets K3 launch) ->
// gridsync (waits K1's g_ae) -> ae loads + FMA. (R12-proven u path.)
// ---------------------------------------------------------------------------
__global__ void k_u(const float* __restrict__ W) {
    int tid = threadIdx.x, lane = tid & 31, wid = tid >> 5;

    int h = blockIdx.x;
    const float4* wrow = (const float4*)(W + (size_t)h * H);
    float4 w[8];
    #pragma unroll
    for (int kc = 0; kc < 8; kc++)
        w[kc] = __ldg(wrow + kc * 32 + lane);   // independent of K1

    cudaTriggerProgrammaticLaunchCompletion();
    cudaGridDependencySynchronize();            // wait for K1's g_ae

    int bbase = wid * 4;
    const float4* a0 = (const float4*)(g_ae + (size_t)(bbase + 0) * H);
    const float4* a1 = (const float4*)(g_ae + (size_t)(bbase + 1) * H);
    const float4* a2 = (const float4*)(g_ae + (size_t)(bbase + 2) * H);
    const float4* a3 = (const float4*)(g_ae + (size_t)(bbase + 3) * H);
    float c0 = 0.f, c1 = 0.f, c2 = 0.f, c3 = 0.f;
    #pragma unroll
    for (int kc = 0; kc < 8; kc++) {
        int ki = kc * 32 + lane;
        c0 += dot4(w[kc], __ldg(a0 + ki));
        c1 += dot4(w[kc], __ldg(a1 + ki));
        c2 += dot4(w[kc], __ldg(a2 + ki));
        c3 += dot4(w[kc], __ldg(a3 + ki));
    }
    #pragma unroll
    for (int off = 16; off; off >>= 1) {
        c0 += __shfl_xor_sync(0xffffffffu, c0, off);
        c1 += __shfl_xor_sync(0xffffffffu, c1, off);
        c2 += __shfl_xor_sync(0xffffffffu, c2, off);
        c3 += __shfl_xor_sync(0xffffffffu, c3, off);
    }
    if (lane == 0) {
        g_u[(size_t)(bbase + 0) * H + h] = c0;
        g_u[(size_t)(bbase + 1) * H + h] = c1;
        g_u[(size_t)(bbase + 2) * H + h] = c2;
        g_u[(size_t)(bbase + 3) * H + h] = c3;
    }
}

// ---------------------------------------------------------------------------
// K3 (PDL secondary): balanced dedup d + scores + softmax (R12-identical).
// Rows are now L2-resident (or in flight) thanks to K1's prefetch.
// ---------------------------------------------------------------------------
__global__ void k_d_scores(const float* __restrict__ seq,
                           const int* __restrict__ rspan,
                           float* __restrict__ out) {
    cudaGridDependencySynchronize();

    int tid = threadIdx.x, lane = tid & 31, wid = tid >> 5;
    int b = blockIdx.x & 31;
    int j = blockIdx.x >> 5;
    int cnt = g_cnt[b];

    const float4* u = (const float4*)(g_u + (size_t)b * H);
    const int* list = g_list + b * S;
    float* drow = g_d + b * S;
    const float4* sbase = (const float4*)(seq + (size_t)b * S * H);

    for (int k = j * 8 + wid; k < cnt; k += GBLK * 8) {
        int s = list[k];
        const float4* row = sbase + s * HV4;
        float acc = 0.f;
        #pragma unroll
        for (int i = 0; i < 8; i++) {
            int idx4 = i * 32 + lane;
            acc += dot4(__ldg(row + idx4), __ldg(u + idx4));
        }
        #pragma unroll
        for (int off = 16; off; off >>= 1)
            acc += __shfl_xor_sync(0xffffffffu, acc, off);
        if (lane == 0) drow[s] = acc;
    }
    __syncthreads();

    __shared__ int s_last;
    if (tid == 0) {
        __threadfence();
        int old = atomicAdd(&g_arrive[b], 1);
        s_last = (old == GBLK - 1);
    }
    __syncthreads();
    if (!s_last) return;
    __threadfence();  // acquire side for g_d

    // ---- scores: 4 threads per rubric (r = tid>>2, jj = tid&3) ----
    __shared__ float sc[R];
    {
        int r = tid >> 2, jj = tid & 3;
        int gi = b * R + r;
        bool m = g_mask[gi] != 0;
        float val = -INFINITY;
        float part = 0.f;
        int r0 = __ldg(rspan + gi * 2), r1 = __ldg(rspan + gi * 2 + 1);
        if (m)
            for (int s = r0 + jj; s < r1; s += 4)
                part += __ldcg(drow + s);
        part += __shfl_xor_sync(0xffffffffu, part, 1);
        part += __shfl_xor_sync(0xffffffffu, part, 2);
        if (m) val = part / (float)(r1 - r0);
        if (jj == 0) sc[r] = val;
    }
    __syncthreads();

    // ---- softmax over 64 by warp 0 (2 values per lane) ----
    if (wid == 0) {
        float x0 = sc[lane], x1 = sc[lane + 32];
        float m = fmaxf(x0, x1);
        #pragma unroll
        for (int off = 16; off; off >>= 1)
            m = fmaxf(m, __shfl_xor_sync(0xffffffffu, m, off));
        float e0 = expf(x0 - m), e1 = expf(x1 - m);  // expf(-inf)=0
        float sum = e0 + e1;
        #pragma unroll
        for (int off = 16; off; off >>= 1)
            sum += __shfl_xor_sync(0xffffffffu, sum, off);
        float invs = 1.0f / sum;
        out[b * R + lane] = e0 * invs;
        out[b * R + lane + 32] = e1 * invs;
    }
}

// ---------------------------------------------------------------------------
// Launch. K2/K3 use programmatic stream serialization (PDL).
// Inputs identified by unique element counts (robust to ordering).
// ---------------------------------------------------------------------------
extern "C" void kernel_launch(void* const* d_in, const int* in_sizes, int n_in,
                              void* d_out, int out_size) {
    const float* seq = nullptr;
    const float* W = nullptr;
    const int* rspan = nullptr;
    const int* aspan = nullptr;
    const unsigned char* mask = nullptr;

    for (int i = 0; i < n_in; i++) {
        switch (in_sizes[i]) {
            case B * S * H: seq   = (const float*)d_in[i]; break;
            case H * H:     W     = (const float*)d_in[i]; break;
            case B * R * 2: rspan = (const int*)d_in[i]; break;
            case B * 2:     aspan = (const int*)d_in[i]; break;
            case B * R:     mask  = (const unsigned char*)d_in[i]; break;
            default: break;  // bias (size 1): cancels in softmax
        }
    }

    float* out = (float*)d_out;

    // K1: normal launch (pooling + mark + L2 prefetch)
    k_prep<<<288 + NPREF, 256>>>(seq, aspan, rspan, mask);

    cudaLaunchAttribute attr[1];
    attr[0].id = cudaLaunchAttributeProgrammaticStreamSerialization;
    attr[0].val.programmaticStreamSerializationAllowed = 1;

    // K2: PDL secondary (u only)
    {
        cudaLaunchConfig_t cfg = {};
        cfg.gridDim = dim3(NUBLK);
        cfg.blockDim = dim3(256);
        cfg.stream = 0;
        cfg.attrs = attr;
        cfg.numAttrs = 1;
        cudaLaunchKernelEx(&cfg, k_u, W);
    }

    // K3: PDL secondary (d + scores + softmax)
    {
        cudaLaunchConfig_t cfg = {};
        cfg.gridDim = dim3(B * GBLK);
        cfg.blockDim = dim3(256);
        cfg.stream = 0;
        cfg.attrs = attr;
        cfg.numAttrs = 1;
        cudaLaunchKernelEx(&cfg, k_d_scores, seq, rspan, out);
    }
}

// round 14
// speedup vs baseline: 1.2235x; 1.2235x over previous
#include <cuda_runtime.h>
#include <math.h>

// Problem constants
#define B 32
#define S 2048
#define H 1024
#define HV4 (H / 4)          // 256 float4 per row
#define R 64
#define GBLK 32              // d-blocks per batch in K3
#define NUBLK 1024           // u blocks in K2 (1 h-row each)
#define MAXT 8               // max tasks per warp in K3 (ceil(2048/256))

// Scratch (no allocations allowed -> __device__ globals)
__device__ float g_ae[B * H];            // answer_emb [B,H]
__device__ float g_u[B * H];             // u = W @ answer_emb, [B,H]
__device__ float g_d[B * S];             // per-unique-row dot d[b,s]
__device__ int   g_list[B * S];          // per-batch compacted touched-row list
__device__ int   g_cnt[B];               // touched-row count per batch
__device__ int   g_arrive[B];            // per-batch arrival counters (K2 zeroes)
__device__ unsigned char g_mask[B * R];  // canonicalized rubric_mask

__device__ __forceinline__ float dot4(float4 a, float4 b) {
    return a.x * b.x + a.y * b.y + a.z * b.z + a.w * b.w;
}

// ---------------------------------------------------------------------------
// K1: answer-span mean pooling, 256 blocks x 512 threads (16 warps).
// Block (b, seg): 32 float4 cols of segment seg; 16 warps stride span rows
// (serial depth <= 2, halved vs R12); smem reduce over 16 warps.
// Triggers PDL completion at entry so K2 overlaps.
// ---------------------------------------------------------------------------
__global__ void k_answer(const float* __restrict__ seq,
                         const int* __restrict__ aspan) {
    cudaTriggerProgrammaticLaunchCompletion();
    int tid = threadIdx.x, lane = tid & 31, wid = tid >> 5;
    int b = blockIdx.x >> 3, seg = blockIdx.x & 7;
    int s0 = __ldg(aspan + 2 * b), s1 = __ldg(aspan + 2 * b + 1);
    const float4* base =
        (const float4*)(seq + (size_t)b * S * H) + seg * 32 + lane;
    float4 a = make_float4(0.f, 0.f, 0.f, 0.f);
    for (int s = s0 + wid; s < s1; s += 16) {
        float4 e = __ldg(base + s * HV4);
        a.x += e.x; a.y += e.y; a.z += e.z; a.w += e.w;
    }
    __shared__ float4 part[16][32];
    part[wid][lane] = a;
    __syncthreads();
    if (tid < 32) {
        float4 acc = part[0][tid];
        #pragma unroll
        for (int w = 1; w < 16; w++) {
            float4 e = part[w][tid];
            acc.x += e.x; acc.y += e.y; acc.z += e.z; acc.w += e.w;
        }
        float inv = 1.0f / (float)(s1 - s0);
        acc.x *= inv; acc.y *= inv; acc.z *= inv; acc.w *= inv;
        ((float4*)g_ae)[b * HV4 + seg * 32 + tid] = acc;
    }
}

// ---------------------------------------------------------------------------
// K2 (PDL secondary): u = W @ ae + independent mark/compact (R12-proven).
//   u blocks [0,1024): preload W row (independent of K1) -> trigger ->
//     gridsync (waits K1's g_ae) -> ae loads + FMA.
//   mark blocks [1024,1056): input-only, no sync, overlap K1.
// ---------------------------------------------------------------------------
__global__ void k_u_mark(const float* __restrict__ W,
                         const int* __restrict__ rspan,
                         const unsigned char* __restrict__ rawmask) {
    int tid = threadIdx.x, lane = tid & 31, wid = tid >> 5;

    if (blockIdx.x < NUBLK) {
        // ---- u producer: one h-row ----
        int h = blockIdx.x;
        const float4* wrow = (const float4*)(W + (size_t)h * H);
        float4 w[8];
        #pragma unroll
        for (int kc = 0; kc < 8; kc++)
            w[kc] = __ldg(wrow + kc * 32 + lane);   // independent of K1

        cudaTriggerProgrammaticLaunchCompletion();
        cudaGridDependencySynchronize();            // wait for K1's g_ae

        int bbase = wid * 4;
        const float4* a0 = (const float4*)(g_ae + (size_t)(bbase + 0) * H);
        const float4* a1 = (const float4*)(g_ae + (size_t)(bbase + 1) * H);
        const float4* a2 = (const float4*)(g_ae + (size_t)(bbase + 2) * H);
        const float4* a3 = (const float4*)(g_ae + (size_t)(bbase + 3) * H);
        float c0 = 0.f, c1 = 0.f, c2 = 0.f, c3 = 0.f;
        #pragma unroll
        for (int kc = 0; kc < 8; kc++) {
            int ki = kc * 32 + lane;
            c0 += dot4(w[kc], __ldg(a0 + ki));
            c1 += dot4(w[kc], __ldg(a1 + ki));
            c2 += dot4(w[kc], __ldg(a2 + ki));
            c3 += dot4(w[kc], __ldg(a3 + ki));
        }
        #pragma unroll
        for (int off = 16; off; off >>= 1) {
            c0 += __shfl_xor_sync(0xffffffffu, c0, off);
            c1 += __shfl_xor_sync(0xffffffffu, c1, off);
            c2 += __shfl_xor_sync(0xffffffffu, c2, off);
            c3 += __shfl_xor_sync(0xffffffffu, c3, off);
        }
        if (lane == 0) {
            g_u[(size_t)(bbase + 0) * H + h] = c0;
            g_u[(size_t)(bbase + 1) * H + h] = c1;
            g_u[(size_t)(bbase + 2) * H + h] = c2;
            g_u[(size_t)(bbase + 3) * H + h] = c3;
        }
        return;
    }

    // ---- mark + compact for batch b: inputs only -> no sync ----
    cudaTriggerProgrammaticLaunchCompletion();
    int b = blockIdx.x - NUBLK;

    // Encoding detection: int32-coded {0,1} has all bytes at i%4!=0 zero;
    // a 1-byte bool mask (~80% true) has nonzero bytes there w.h.p.
    __shared__ int s_any;
    if (tid == 0) s_any = 0;
    __syncthreads();
    int any = 0;
    for (int i = tid; i < B * R; i += 256)
        if (i & 3) any |= rawmask[i];
    if (any) atomicOr(&s_any, 1);
    __syncthreads();
    const int is_bool = s_any;
    const int* raw32 = (const int*)rawmask;

    __shared__ unsigned char fl[S];
    for (int i = tid; i < S / 4; i += 256) ((int*)fl)[i] = 0;
    __syncthreads();

    // 4 threads per rubric: r = tid>>2, phase jj = tid&3 (same-value byte
    // writes from overlapping rubrics are benign).
    {
        int r = tid >> 2, jj = tid & 3;
        int gi = b * R + r;
        unsigned char m = is_bool ? (rawmask[gi] != 0) : (raw32[gi] != 0);
        if (jj == 0) g_mask[gi] = m;
        if (m) {
            int r0 = __ldg(rspan + gi * 2), r1 = __ldg(rspan + gi * 2 + 1);
            for (int s = r0 + jj; s < r1; s += 4) fl[s] = 1;
        }
    }
    __syncthreads();

    // compact: thread t owns positions [t*8, t*8+8)
    int basep = tid * 8;
    int c = 0;
    #pragma unroll
    for (int k = 0; k < 8; k++) c += fl[basep + k];

    int v = c;
    #pragma unroll
    for (int o = 1; o < 32; o <<= 1) {
        int n = __shfl_up_sync(0xffffffffu, v, o);
        if (lane >= o) v += n;
    }
    __shared__ int wsum[8], wpref[9];
    if (lane == 31) wsum[wid] = v;
    __syncthreads();
    if (tid == 0) {
        int acc = 0;
        for (int w = 0; w < 8; w++) { wpref[w] = acc; acc += wsum[w]; }
        wpref[8] = acc;
    }
    __syncthreads();

    int rank = wpref[wid] + v - c;  // exclusive prefix
    int* list = g_list + b * S;
    #pragma unroll
    for (int k = 0; k < 8; k++)
        if (fl[basep + k]) list[rank++] = basep + k;

    if (tid == 0) {
        g_cnt[b] = wpref[8];
        g_arrive[b] = 0;
    }
}

// ---------------------------------------------------------------------------
// K3 (PDL secondary): balanced dedup d + scores + softmax.
// Change vs R12: each warp loads ALL its list entries up front (independent
// L2 loads, no serial list->rows bubble between tasks), then runs row loops.
// ---------------------------------------------------------------------------
__global__ void k_d_scores(const float* __restrict__ seq,
                           const int* __restrict__ rspan,
                           float* __restrict__ out) {
    cudaGridDependencySynchronize();

    int tid = threadIdx.x, lane = tid & 31, wid = tid >> 5;
    int b = blockIdx.x & 31;
    int j = blockIdx.x >> 5;
    int cnt = g_cnt[b];

    const float4* u = (const float4*)(g_u + (size_t)b * H);
    const int* list = g_list + b * S;
    float* drow = g_d + b * S;
    const float4* sbase = (const float4*)(seq + (size_t)b * S * H);

    // hoist list loads: independent, overlapped
    int ss[MAXT];
    int nt = 0;
    #pragma unroll
    for (int t = 0; t < MAXT; t++) {
        int k = j * 8 + wid + t * (GBLK * 8);
        if (k < cnt) { ss[t] = __ldg(list + k); nt = t + 1; }
    }

    for (int t = 0; t < nt; t++) {
        int s = ss[t];
        const float4* row = sbase + s * HV4;
        float acc = 0.f;
        #pragma unroll
        for (int i = 0; i < 8; i++) {
            int idx4 = i * 32 + lane;
            acc += dot4(__ldg(row + idx4), __ldg(u + idx4));
        }
        #pragma unroll
        for (int off = 16; off; off >>= 1)
            acc += __shfl_xor_sync(0xffffffffu, acc, off);
        if (lane == 0) drow[s] = acc;
    }
    __syncthreads();

    __shared__ int s_last;
    if (tid == 0) {
        __threadfence();
        int old = atomicAdd(&g_arrive[b], 1);
        s_last = (old == GBLK - 1);
    }
    __syncthreads();
    if (!s_last) return;
    __threadfence();  // acquire side for g_d

    // ---- scores: 4 threads per rubric (r = tid>>2, jj = tid&3) ----
    __shared__ float sc[R];
    {
        int r = tid >> 2, jj = tid & 3;
        int gi = b * R + r;
        bool m = g_mask[gi] != 0;
        float val = -INFINITY;
        float part = 0.f;
        int r0 = __ldg(rspan + gi * 2), r1 = __ldg(rspan + gi * 2 + 1);
        if (m)
            for (int s = r0 + jj; s < r1; s += 4)
                part += __ldcg(drow + s);
        part += __shfl_xor_sync(0xffffffffu, part, 1);
        part += __shfl_xor_sync(0xffffffffu, part, 2);
        if (m) val = part / (float)(r1 - r0);
        if (jj == 0) sc[r] = val;
    }
    __syncthreads();

    // ---- softmax over 64 by warp 0 (2 values per lane) ----
    if (wid == 0) {
        float x0 = sc[lane], x1 = sc[lane + 32];
        float m = fmaxf(x0, x1);
        #pragma unroll
        for (int off = 16; off; off >>= 1)
            m = fmaxf(m, __shfl_xor_sync(0xffffffffu, m, off));
        float e0 = expf(x0 - m), e1 = expf(x1 - m);  // expf(-inf)=0
        float sum = e0 + e1;
        #pragma unroll
        for (int off = 16; off; off >>= 1)
            sum += __shfl_xor_sync(0xffffffffu, sum, off);
        float invs = 1.0f / sum;
        out[b * R + lane] = e0 * invs;
        out[b * R + lane + 32] = e1 * invs;
    }
}

// ---------------------------------------------------------------------------
// Launch. K2/K3 use programmatic stream serialization (PDL).
// Inputs identified by unique element counts (robust to ordering).
// ---------------------------------------------------------------------------
extern "C" void kernel_launch(void* const* d_in, const int* in_sizes, int n_in,
                              void* d_out, int out_size) {
    const float* seq = nullptr;
    const float* W = nullptr;
    const int* rspan = nullptr;
    const int* aspan = nullptr;
    const unsigned char* mask = nullptr;

    for (int i = 0; i < n_in; i++) {
        switch (in_sizes[i]) {
            case B * S * H: seq   = (const float*)d_in[i]; break;
            case H * H:     W     = (const float*)d_in[i]; break;
            case B * R * 2: rspan = (const int*)d_in[i]; break;
            case B * 2:     aspan = (const int*)d_in[i]; break;
            case B * R:     mask  = (const unsigned char*)d_in[i]; break;
            default: break;  // bias (size 1): cancels in softmax
        }
    }

    float* out = (float*)d_out;

    // K1: normal launch (answer pooling, 512 threads)
    k_answer<<<256, 512>>>(seq, aspan);

    cudaLaunchAttribute attr[1];
    attr[0].id = cudaLaunchAttributeProgrammaticStreamSerialization;
    attr[0].val.programmaticStreamSerializationAllowed = 1;

    // K2: PDL secondary (u + mark)
    {
        cudaLaunchConfig_t cfg = {};
        cfg.gridDim = dim3(NUBLK + B);
        cfg.blockDim = dim3(256);
        cfg.stream = 0;
        cfg.attrs = attr;
        cfg.numAttrs = 1;
        cudaLaunchKernelEx(&cfg, k_u_mark, W, rspan, mask);
    }

    // K3: PDL secondary (d + scores + softmax)
    {
        cudaLaunchConfig_t cfg = {};
        cfg.gridDim = dim3(B * GBLK);
        cfg.blockDim = dim3(256);
        cfg.stream = 0;
        cfg.attrs = attr;
        cfg.numAttrs = 1;
        cudaLaunchKernelEx(&cfg, k_d_scores, seq, rspan, out);
    }
}

// round 15
// speedup vs baseline: 1.3330x; 1.0895x over previous
#include <cuda_runtime.h>
#include <math.h>

// Problem constants
#define B 32
#define S 2048
#define H 1024
#define HV4 (H / 4)          // 256 float4 per row
#define R 64
#define GBLK 32              // d-blocks per batch in K3
#define NUBLK 1024           // u blocks in K2 (1 h-row each)

// Scratch (no allocations allowed -> __device__ globals)
__device__ float g_ae[B * H];            // answer_emb [B,H]
__device__ float g_u[B * H];             // u = W @ answer_emb, [B,H]
__device__ float g_d[B * S];             // per-unique-row dot d[b,s]
__device__ int   g_list[B * S];          // per-batch compacted touched-row list
__device__ int   g_cnt[B];               // touched-row count per batch
__device__ int   g_arrive[B];            // per-batch arrival counters (K2 zeroes)
__device__ unsigned char g_mask[B * R];  // canonicalized rubric_mask

__device__ __forceinline__ float dot4(float4 a, float4 b) {
    return a.x * b.x + a.y * b.y + a.z * b.z + a.w * b.w;
}

// ---------------------------------------------------------------------------
// K1: answer-span mean pooling, 256 blocks x 512 threads (16 warps).
// Block (b, seg): 32 float4 cols of segment seg; 16 warps stride span rows
// (serial depth <= 2); smem reduce over 16 warps. Triggers PDL completion at
// entry so K2 overlaps. (R14's K1 — measured faster than the 256-thread one.)
// ---------------------------------------------------------------------------
__global__ void k_answer(const float* __restrict__ seq,
                         const int* __restrict__ aspan) {
    cudaTriggerProgrammaticLaunchCompletion();
    int tid = threadIdx.x, lane = tid & 31, wid = tid >> 5;
    int b = blockIdx.x >> 3, seg = blockIdx.x & 7;
    int s0 = __ldg(aspan + 2 * b), s1 = __ldg(aspan + 2 * b + 1);
    const float4* base =
        (const float4*)(seq + (size_t)b * S * H) + seg * 32 + lane;
    float4 a = make_float4(0.f, 0.f, 0.f, 0.f);
    for (int s = s0 + wid; s < s1; s += 16) {
        float4 e = __ldg(base + s * HV4);
        a.x += e.x; a.y += e.y; a.z += e.z; a.w += e.w;
    }
    __shared__ float4 part[16][32];
    part[wid][lane] = a;
    __syncthreads();
    if (tid < 32) {
        float4 acc = part[0][tid];
        #pragma unroll
        for (int w = 1; w < 16; w++) {
            float4 e = part[w][tid];
            acc.x += e.x; acc.y += e.y; acc.z += e.z; acc.w += e.w;
        }
        float inv = 1.0f / (float)(s1 - s0);
        acc.x *= inv; acc.y *= inv; acc.z *= inv; acc.w *= inv;
        ((float4*)g_ae)[b * HV4 + seg * 32 + tid] = acc;
    }
}

// ---------------------------------------------------------------------------
// K2 (PDL secondary): u = W @ ae + independent mark/compact (R12-proven).
//   u blocks [0,1024): preload W row (independent of K1) -> trigger ->
//     gridsync (waits K1's g_ae) -> ae loads + FMA.
//   mark blocks [1024,1056): input-only, no sync, overlap K1.
// ---------------------------------------------------------------------------
__global__ void k_u_mark(const float* __restrict__ W,
                         const int* __restrict__ rspan,
                         const unsigned char* __restrict__ rawmask) {
    int tid = threadIdx.x, lane = tid & 31, wid = tid >> 5;

    if (blockIdx.x < NUBLK) {
        // ---- u producer: one h-row ----
        int h = blockIdx.x;
        const float4* wrow = (const float4*)(W + (size_t)h * H);
        float4 w[8];
        #pragma unroll
        for (int kc = 0; kc < 8; kc++)
            w[kc] = __ldg(wrow + kc * 32 + lane);   // independent of K1

        cudaTriggerProgrammaticLaunchCompletion();
        cudaGridDependencySynchronize();            // wait for K1's g_ae

        int bbase = wid * 4;
        const float4* a0 = (const float4*)(g_ae + (size_t)(bbase + 0) * H);
        const float4* a1 = (const float4*)(g_ae + (size_t)(bbase + 1) * H);
        const float4* a2 = (const float4*)(g_ae + (size_t)(bbase + 2) * H);
        const float4* a3 = (const float4*)(g_ae + (size_t)(bbase + 3) * H);
        float c0 = 0.f, c1 = 0.f, c2 = 0.f, c3 = 0.f;
        #pragma unroll
        for (int kc = 0; kc < 8; kc++) {
            int ki = kc * 32 + lane;
            c0 += dot4(w[kc], __ldg(a0 + ki));
            c1 += dot4(w[kc], __ldg(a1 + ki));
            c2 += dot4(w[kc], __ldg(a2 + ki));
            c3 += dot4(w[kc], __ldg(a3 + ki));
        }
        #pragma unroll
        for (int off = 16; off; off >>= 1) {
            c0 += __shfl_xor_sync(0xffffffffu, c0, off);
            c1 += __shfl_xor_sync(0xffffffffu, c1, off);
            c2 += __shfl_xor_sync(0xffffffffu, c2, off);
            c3 += __shfl_xor_sync(0xffffffffu, c3, off);
        }
        if (lane == 0) {
            g_u[(size_t)(bbase + 0) * H + h] = c0;
            g_u[(size_t)(bbase + 1) * H + h] = c1;
            g_u[(size_t)(bbase + 2) * H + h] = c2;
            g_u[(size_t)(bbase + 3) * H + h] = c3;
        }
        return;
    }

    // ---- mark + compact for batch b: inputs only -> no sync ----
    cudaTriggerProgrammaticLaunchCompletion();
    int b = blockIdx.x - NUBLK;

    // Encoding detection: int32-coded {0,1} has all bytes at i%4!=0 zero;
    // a 1-byte bool mask (~80% true) has nonzero bytes there w.h.p.
    __shared__ int s_any;
    if (tid == 0) s_any = 0;
    __syncthreads();
    int any = 0;
    for (int i = tid; i < B * R; i += 256)
        if (i & 3) any |= rawmask[i];
    if (any) atomicOr(&s_any, 1);
    __syncthreads();
    const int is_bool = s_any;
    const int* raw32 = (const int*)rawmask;

    __shared__ unsigned char fl[S];
    for (int i = tid; i < S / 4; i += 256) ((int*)fl)[i] = 0;
    __syncthreads();

    // 4 threads per rubric: r = tid>>2, phase jj = tid&3 (same-value byte
    // writes from overlapping rubrics are benign).
    {
        int r = tid >> 2, jj = tid & 3;
        int gi = b * R + r;
        unsigned char m = is_bool ? (rawmask[gi] != 0) : (raw32[gi] != 0);
        if (jj == 0) g_mask[gi] = m;
        if (m) {
            int r0 = __ldg(rspan + gi * 2), r1 = __ldg(rspan + gi * 2 + 1);
            for (int s = r0 + jj; s < r1; s += 4) fl[s] = 1;
        }
    }
    __syncthreads();

    // compact: thread t owns positions [t*8, t*8+8)
    int basep = tid * 8;
    int c = 0;
    #pragma unroll
    for (int k = 0; k < 8; k++) c += fl[basep + k];

    int v = c;
    #pragma unroll
    for (int o = 1; o < 32; o <<= 1) {
        int n = __shfl_up_sync(0xffffffffu, v, o);
        if (lane >= o) v += n;
    }
    __shared__ int wsum[8], wpref[9];
    if (lane == 31) wsum[wid] = v;
    __syncthreads();
    if (tid == 0) {
        int acc = 0;
        for (int w = 0; w < 8; w++) { wpref[w] = acc; acc += wsum[w]; }
        wpref[8] = acc;
    }
    __syncthreads();

    int rank = wpref[wid] + v - c;  // exclusive prefix
    int* list = g_list + b * S;
    #pragma unroll
    for (int k = 0; k < 8; k++)
        if (fl[basep + k]) list[rank++] = basep + k;

    if (tid == 0) {
        g_cnt[b] = wpref[8];
        g_arrive[b] = 0;
    }
}

// ---------------------------------------------------------------------------
// K3 (PDL secondary): balanced dedup d + scores + softmax (R12-identical
// structure; only change: seq rows via __ldcs — each unique row is read
// exactly once after dedup, so evict-first avoids useless L2 retention).
// ---------------------------------------------------------------------------
__global__ void k_d_scores(const float* __restrict__ seq,
                           const int* __restrict__ rspan,
                           float* __restrict__ out) {
    cudaGridDependencySynchronize();

    int tid = threadIdx.x, lane = tid & 31, wid = tid >> 5;
    int b = blockIdx.x & 31;
    int j = blockIdx.x >> 5;
    int cnt = g_cnt[b];

    const float4* u = (const float4*)(g_u + (size_t)b * H);
    const int* list = g_list + b * S;
    float* drow = g_d + b * S;
    const float4* sbase = (const float4*)(seq + (size_t)b * S * H);

    for (int k = j * 8 + wid; k < cnt; k += GBLK * 8) {
        int s = list[k];
        const float4* row = sbase + s * HV4;
        float acc = 0.f;
        #pragma unroll
        for (int i = 0; i < 8; i++) {
            int idx4 = i * 32 + lane;
            acc += dot4(__ldcs(row + idx4), __ldg(u + idx4));
        }
        #pragma unroll
        for (int off = 16; off; off >>= 1)
            acc += __shfl_xor_sync(0xffffffffu, acc, off);
        if (lane == 0) drow[s] = acc;
    }
    __syncthreads();

    __shared__ int s_last;
    if (tid == 0) {
        __threadfence();
        int old = atomicAdd(&g_arrive[b], 1);
        s_last = (old == GBLK - 1);
    }
    __syncthreads();
    if (!s_last) return;
    __threadfence();  // acquire side for g_d

    // ---- scores: 4 threads per rubric (r = tid>>2, jj = tid&3) ----
    __shared__ float sc[R];
    {
        int r = tid >> 2, jj = tid & 3;
        int gi = b * R + r;
        bool m = g_mask[gi] != 0;
        float val = -INFINITY;
        float part = 0.f;
        int r0 = __ldg(rspan + gi * 2), r1 = __ldg(rspan + gi * 2 + 1);
        if (m)
            for (int s = r0 + jj; s < r1; s += 4)
                part += __ldcg(drow + s);
        part += __shfl_xor_sync(0xffffffffu, part, 1);
        part += __shfl_xor_sync(0xffffffffu, part, 2);
        if (m) val = part / (float)(r1 - r0);
        if (jj == 0) sc[r] = val;
    }
    __syncthreads();

    // ---- softmax over 64 by warp 0 (2 values per lane) ----
    if (wid == 0) {
        float x0 = sc[lane], x1 = sc[lane + 32];
        float m = fmaxf(x0, x1);
        #pragma unroll
        for (int off = 16; off; off >>= 1)
            m = fmaxf(m, __shfl_xor_sync(0xffffffffu, m, off));
        float e0 = expf(x0 - m), e1 = expf(x1 - m);  // expf(-inf)=0
        float sum = e0 + e1;
        #pragma unroll
        for (int off = 16; off; off >>= 1)
            sum += __shfl_xor_sync(0xffffffffu, sum, off);
        float invs = 1.0f / sum;
        out[b * R + lane] = e0 * invs;
        out[b * R + lane + 32] = e1 * invs;
    }
}

// ---------------------------------------------------------------------------
// Launch. K2/K3 use programmatic stream serialization (PDL).
// Inputs identified by unique element counts (robust to ordering).
// ---------------------------------------------------------------------------
extern "C" void kernel_launch(void* const* d_in, const int* in_sizes, int n_in,
                              void* d_out, int out_size) {
    const float* seq = nullptr;
    const float* W = nullptr;
    const int* rspan = nullptr;
    const int* aspan = nullptr;
    const unsigned char* mask = nullptr;

    for (int i = 0; i < n_in; i++) {
        switch (in_sizes[i]) {
            case B * S * H: seq   = (const float*)d_in[i]; break;
            case H * H:     W     = (const float*)d_in[i]; break;
            case B * R * 2: rspan = (const int*)d_in[i]; break;
            case B * 2:     aspan = (const int*)d_in[i]; break;
            case B * R:     mask  = (const unsigned char*)d_in[i]; break;
            default: break;  // bias (size 1): cancels in softmax
        }
    }

    float* out = (float*)d_out;

    // K1: normal launch (answer pooling, 512 threads)
    k_answer<<<256, 512>>>(seq, aspan);

    cudaLaunchAttribute attr[1];
    attr[0].id = cudaLaunchAttributeProgrammaticStreamSerialization;
    attr[0].val.programmaticStreamSerializationAllowed = 1;

    // K2: PDL secondary (u + mark)
    {
        cudaLaunchConfig_t cfg = {};
        cfg.gridDim = dim3(NUBLK + B);
        cfg.blockDim = dim3(256);
        cfg.stream = 0;
        cfg.attrs = attr;
        cfg.numAttrs = 1;
        cudaLaunchKernelEx(&cfg, k_u_mark, W, rspan, mask);
    }

    // K3: PDL secondary (d + scores + softmax)
    {
        cudaLaunchConfig_t cfg = {};
        cfg.gridDim = dim3(B * GBLK);
        cfg.blockDim = dim3(256);
        cfg.stream = 0;
        cfg.attrs = attr;
        cfg.numAttrs = 1;
        cudaLaunchKernelEx(&cfg, k_d_scores, seq, rspan, out);
    }
}